// round 10
// baseline (speedup 1.0000x reference)
#include <cuda_runtime.h>
#include <cuda_fp16.h>
#include <cstdint>

// ---------------------------------------------------------------------------
// 2D DCT-II, two-level parity folding, fp16 mma.sync, 64x64 warp tiles,
// 4-stage cp.async pipeline. Two kernels (pass A, pass B), each with:
//   odd jobs (bid<512):   128x256x256  (q odd, all 256 at once), warp 64x64
//   even jobs (bid>=512): 128x128x128  (q=4s / q=4s+2),          warp 64x32
// Pass A folds img in the loader (register path), epilogue emits prefolded
// U1/U00/U01 fp16. Pass B is a pure cp.async GEMM.
// ---------------------------------------------------------------------------

#define DCT_N 512
#define BATCH 128
#define BKC   32
#define APH   40             // A smem pitch (halfs), 128 rows x 32 k
#define BPH   264            // B smem pitch (halfs), 32 rows x <=256 n
#define SPF   132            // epilogue staging pitch (floats)

#define A_ST_BYTES (128 * APH * 2)            // 10240
#define B_ST_BYTES (32 * BPH * 2)             // 16896
#define ST_BYTES   (A_ST_BYTES + B_ST_BYTES)  // 27136 (x4 stages = 108544)
#define SMEM_BYTES (256 * SPF * 4)            // 135168 staging dominates

__device__ __align__(16) __half g_T1 [256 * 256];   // [n][r] cos(pi(2n+1)(2r+1)/1024)
__device__ __align__(16) __half g_TEE[128 * 128];   // [n][s] cos(pi(2n+1)s/256)
__device__ __align__(16) __half g_TEO[128 * 128];   // [n][s] cos(pi(2n+1)(2s+1)/512)
__device__ __align__(16) __half g_U1 [(size_t)BATCH * DCT_N * 256];
__device__ __align__(16) __half g_U00[(size_t)BATCH * DCT_N * 128];
__device__ __align__(16) __half g_U01[(size_t)BATCH * DCT_N * 128];

__global__ void init_tables_kernel() {
    int idx = blockIdx.x * blockDim.x + threadIdx.x;
    if (idx < 256 * 256) {
        int n = idx >> 8, r = idx & 255;
        g_T1[idx] = __float2half_rn(
            cospif((2.0f * n + 1.0f) * (2.0f * r + 1.0f) * (1.0f / 1024.0f)));
    } else if (idx < 256 * 256 + 128 * 128) {
        int j = idx - 256 * 256;
        int n = j >> 7, s = j & 127;
        g_TEE[j] = __float2half_rn(
            cospif((2.0f * n + 1.0f) * (float)s * (1.0f / 256.0f)));
    } else if (idx < 256 * 256 + 2 * 128 * 128) {
        int j = idx - 256 * 256 - 128 * 128;
        int n = j >> 7, s = j & 127;
        g_TEO[j] = __float2half_rn(
            cospif((2.0f * n + 1.0f) * (2.0f * s + 1.0f) * (1.0f / 512.0f)));
    }
}

__device__ __forceinline__ uint32_t smem_u32(const void* p) {
    uint32_t a;
    asm("{ .reg .u64 t; cvta.to.shared.u64 t, %1; cvt.u32.u64 %0, t; }" : "=r"(a) : "l"(p));
    return a;
}
__device__ __forceinline__ void cp16(uint32_t dst, const void* src) {
    asm volatile("cp.async.cg.shared.global [%0], [%1], 16;" :: "r"(dst), "l"(src));
}
#define CP_COMMIT() asm volatile("cp.async.commit_group;" ::: "memory")
#define CP_WAIT(n)  asm volatile("cp.async.wait_group %0;" :: "n"(n) : "memory")

__device__ __forceinline__ void ldsm4(uint32_t r[4], uint32_t addr) {
    asm volatile("ldmatrix.sync.aligned.m8n8.x4.shared.b16 {%0,%1,%2,%3}, [%4];"
                 : "=r"(r[0]), "=r"(r[1]), "=r"(r[2]), "=r"(r[3]) : "r"(addr));
}
__device__ __forceinline__ void ldsm4t(uint32_t r[4], uint32_t addr) {
    asm volatile("ldmatrix.sync.aligned.m8n8.x4.trans.shared.b16 {%0,%1,%2,%3}, [%4];"
                 : "=r"(r[0]), "=r"(r[1]), "=r"(r[2]), "=r"(r[3]) : "r"(addr));
}
__device__ __forceinline__ void mma_f16(float c[4], const uint32_t a[4],
                                        uint32_t b0, uint32_t b1) {
    asm volatile(
        "mma.sync.aligned.m16n8k16.row.col.f32.f16.f16.f32 "
        "{%0,%1,%2,%3},{%4,%5,%6,%7},{%8,%9},{%0,%1,%2,%3};"
        : "+f"(c[0]), "+f"(c[1]), "+f"(c[2]), "+f"(c[3])
        : "r"(a[0]), "r"(a[1]), "r"(a[2]), "r"(a[3]), "r"(b0), "r"(b1));
}
__device__ __forceinline__ uint32_t packh2(float lo, float hi) {
    __half2 h = __floats2half2_rn(lo, hi);
    return *(uint32_t*)&h;
}

// PASS 0: A = img (folded in regs), out = U1/U00/U01 fp16
// PASS 1: A = U* (pure cp.async),   out = d_out fp32 scaled
template <int PASS>
__global__ __launch_bounds__(256)
void dct_k(const float* __restrict__ img, float* __restrict__ out)
{
    extern __shared__ __align__(16) char smem[];
    const uint32_t sb = smem_u32(smem);
    float* Sf = (float*)smem;

    const int tid = threadIdx.x, lane = tid & 31, warp = tid >> 5;
    const int bid = blockIdx.x;
    const bool ODD = (bid < 512);
    int bat, yb, br;
    if (ODD) { bat = bid >> 2; yb = bid & 3; br = 0; }
    else     { int e = bid - 512; bat = e >> 3; yb = (e >> 1) & 3; br = e & 1; }

    const int NC = ODD ? 8 : 4;               // k chunks of 32
    const int TW = ODD ? 256 : 128;           // table width
    const __half* tbl = ODD ? g_T1 : (br == 0 ? g_TEE : g_TEO);
    const float sg2 = (br == 1) ? -1.0f : 1.0f;
    const int wm = (warp & 1) * 64;
    const int wn = (warp >> 1) * (ODD ? 64 : 32);
    const int grp = lane >> 2, tig = lane & 3;

    const float* Ef = img + (size_t)bat * DCT_N * DCT_N;
    const __half* Ub = ODD ? g_U1 + (size_t)bat * DCT_N * 256
                           : (br == 0 ? g_U00 : g_U01) + (size_t)bat * DCT_N * 128;
    const int UW = ODD ? 256 : 128;
    float* Of = out + (size_t)bat * DCT_N * DCT_N;

    const int aLaneOff =
        ((wm + (lane & 7) + ((lane >> 3) & 1) * 8) * APH + (lane >> 4) * 8) * 2;
    const int bLaneOff =
        (((((lane >> 4) & 1) * 8) + (lane & 7)) * BPH + ((lane >> 3) & 1) * 8) * 2;

    float acc[4][8][4];
#pragma unroll
    for (int mi = 0; mi < 4; ++mi)
#pragma unroll
        for (int ni = 0; ni < 8; ++ni)
#pragma unroll
            for (int r = 0; r < 4; ++r) acc[mi][ni][r] = 0.0f;

    // A-loader coords: 128 rows x 4 granules(8h) -> 2 per thread
    int rowA[2], kh[2];
    const float* rowPtr[2];
#pragma unroll
    for (int i = 0; i < 2; ++i) {
        int g = tid + i * 256;
        rowA[i] = g >> 2;
        kh[i] = (g & 3) * 8;
        if (PASS == 0) {
            int l = rowA[i];
            int j0 = 32 * yb + (l & 31);
            int quad = l >> 5;
            int gi = (quad == 0) ? j0
                   : (quad == 1) ? 511 - j0
                   : (quad == 2) ? 255 - j0
                                 : 256 + j0;
            rowPtr[i] = Ef + (size_t)gi * DCT_N;
        }
    }

    uint4 oReg[2];
    auto ldA = [&](int t) {   // PASS 0: fold img -> fp16 regs
#pragma unroll
        for (int i = 0; i < 2; ++i) {
            int kp = t * BKC + kh[i];
            const float* base = rowPtr[i];
            float4 F0 = *(const float4*)(base + kp);
            float4 F1 = *(const float4*)(base + kp + 4);
            float4 R1 = *(const float4*)(base + 508 - kp);
            float4 R0 = *(const float4*)(base + 504 - kp);
            if (ODD) {
                oReg[i].x = packh2(F0.x - R1.w, F0.y - R1.z);
                oReg[i].y = packh2(F0.z - R1.y, F0.w - R1.x);
                oReg[i].z = packh2(F1.x - R0.w, F1.y - R0.z);
                oReg[i].w = packh2(F1.z - R0.y, F1.w - R0.x);
            } else {
                float4 C1 = *(const float4*)(base + 252 - kp);
                float4 C0 = *(const float4*)(base + 248 - kp);
                float4 D0 = *(const float4*)(base + 256 + kp);
                float4 D1 = *(const float4*)(base + 260 + kp);
                oReg[i].x = packh2(fmaf(sg2, C1.w + D0.x, F0.x + R1.w),
                                   fmaf(sg2, C1.z + D0.y, F0.y + R1.z));
                oReg[i].y = packh2(fmaf(sg2, C1.y + D0.z, F0.z + R1.y),
                                   fmaf(sg2, C1.x + D0.w, F0.w + R1.x));
                oReg[i].z = packh2(fmaf(sg2, C0.w + D1.x, F1.x + R0.w),
                                   fmaf(sg2, C0.z + D1.y, F1.y + R0.z));
                oReg[i].w = packh2(fmaf(sg2, C0.y + D1.z, F1.z + R0.y),
                                   fmaf(sg2, C0.x + D1.w, F1.w + R0.x));
            }
        }
    };
    auto stsA = [&](uint32_t off) {
#pragma unroll
        for (int i = 0; i < 2; ++i)
            *(uint4*)(smem + off + (rowA[i] * APH + kh[i]) * 2) = oReg[i];
    };
    auto cpA = [&](int t, uint32_t off) {   // PASS 1: pure async
#pragma unroll
        for (int i = 0; i < 2; ++i) {
            uint32_t dst = sb + off + (rowA[i] * APH + kh[i]) * 2;
            const __half* src = Ub + (size_t)(yb * 128 + rowA[i]) * UW + t * BKC + kh[i];
            cp16(dst, src);
        }
    };
    auto cpB = [&](int t, uint32_t off) {
        if (ODD) {
#pragma unroll
            for (int i = 0; i < 4; ++i) {
                int g = tid + i * 256;
                int r = g >> 5, n = (g & 31) * 8;
                cp16(sb + off + (r * BPH + n) * 2,
                     tbl + (size_t)(t * BKC + r) * TW + n);
            }
        } else {
#pragma unroll
            for (int i = 0; i < 2; ++i) {
                int g = tid + i * 256;
                int r = g >> 4, n = (g & 15) * 8;
                cp16(sb + off + (r * BPH + n) * 2,
                     tbl + (size_t)(t * BKC + r) * TW + n);
            }
        }
    };
    auto compute = [&](uint32_t aOff, uint32_t bOff) {
#pragma unroll
        for (int ks = 0; ks < 2; ++ks) {
            uint32_t a[4][4];
#pragma unroll
            for (int mi = 0; mi < 4; ++mi)
                ldsm4(a[mi], sb + aOff + aLaneOff + mi * (16 * APH * 2) + ks * 32);
            uint32_t bq[4][4];
#pragma unroll
            for (int pr = 0; pr < 4; ++pr)
                if (ODD || pr < 2)
                    ldsm4t(bq[pr], sb + bOff + bLaneOff + ks * (16 * BPH * 2)
                                   + (wn + pr * 16) * 2);
#pragma unroll
            for (int mi = 0; mi < 4; ++mi)
#pragma unroll
                for (int ni = 0; ni < 8; ++ni)
                    if (ODD || ni < 4)
                        mma_f16(acc[mi][ni], a[mi],
                                bq[ni >> 1][ni & 1], bq[ni >> 1][2 + (ni & 1)]);
        }
    };

    uint32_t aOff[4], bOff[4];
#pragma unroll
    for (int s = 0; s < 4; ++s) {
        aOff[s] = s * ST_BYTES;
        bOff[s] = aOff[s] + A_ST_BYTES;
    }

    // ---- prologue: 3 stages ----
    if (PASS == 0) {
        ldA(0); stsA(aOff[0]); cpB(0, bOff[0]); CP_COMMIT();
        ldA(1); stsA(aOff[1]); cpB(1, bOff[1]); CP_COMMIT();
        ldA(2); stsA(aOff[2]); cpB(2, bOff[2]); CP_COMMIT();
        if (3 < NC) ldA(3);
    } else {
        cpA(0, aOff[0]); cpB(0, bOff[0]); CP_COMMIT();
        cpA(1, aOff[1]); cpB(1, bOff[1]); CP_COMMIT();
        cpA(2, aOff[2]); cpB(2, bOff[2]); CP_COMMIT();
    }

    // ---- mainloop: one barrier per chunk ----
#pragma unroll 1
    for (int t = 0; t < NC; ++t) {
        if (t + 3 <= NC - 1)      { CP_WAIT(2); }
        else if (t + 2 <= NC - 1) { CP_WAIT(1); }
        else                      { CP_WAIT(0); }
        __syncthreads();
        if (t + 3 < NC) {
            if (PASS == 0) stsA(aOff[(t + 3) & 3]);
            else           cpA(t + 3, aOff[(t + 3) & 3]);
            cpB(t + 3, bOff[(t + 3) & 3]);
            CP_COMMIT();
            if (PASS == 0 && t + 4 < NC) ldA(t + 4);
        }
        compute(aOff[t & 3], bOff[t & 3]);
    }
    __syncthreads();

    // ---- epilogue: stage acc tile fp32 (Sf[rl][ii]) ----
#pragma unroll
    for (int mi = 0; mi < 4; ++mi)
#pragma unroll
        for (int ni = 0; ni < 8; ++ni)
            if (ODD || ni < 4)
#pragma unroll
                for (int h = 0; h < 2; ++h)
#pragma unroll
                    for (int c = 0; c < 2; ++c) {
                        int rl = wn + ni * 8 + 2 * tig + c;
                        int ii = wm + mi * 16 + grp + 8 * h;
                        Sf[rl * SPF + ii] = acc[mi][ni][2 * h + c];
                    }
    __syncthreads();

    const float is2 = 0.70710678118654752440f;
    if (PASS == 0) {
        __half* U1w  = g_U1  + (size_t)bat * DCT_N * 256;
        __half* U00w = g_U00 + (size_t)bat * DCT_N * 128;
        __half* U01w = g_U01 + (size_t)bat * DCT_N * 128;
        const int eit = ODD ? 8 : 4;
#pragma unroll 1
        for (int it = 0; it < eit; ++it) {
            int idx = it * 256 + tid;
            int rl = idx >> 3;
            int jj4 = (idx & 7) * 4;
            int q = ODD ? (2 * rl + 1) : (br == 0 ? 4 * rl : 4 * rl + 2);
            int j0 = 32 * yb + jj4;
            const float* Sr = Sf + rl * SPF;
            float4 a = *(const float4*)(Sr + jj4);        // T[j0..]
            float4 b = *(const float4*)(Sr + 32 + jj4);   // T[511-j0..]
            float4 c = *(const float4*)(Sr + 64 + jj4);   // T[255-j0..]
            float4 d = *(const float4*)(Sr + 96 + jj4);   // T[256+j0..]
            uint2 u1f, u1r, u00, u01;
            u1f.x = packh2(a.x - b.x, a.y - b.y);
            u1f.y = packh2(a.z - b.z, a.w - b.w);
            u1r.x = packh2(c.w - d.w, c.z - d.z);
            u1r.y = packh2(c.y - d.y, c.x - d.x);
            float e0 = a.x + b.x, e1 = a.y + b.y, e2 = a.z + b.z, e3 = a.w + b.w;
            float f0 = c.x + d.x, f1 = c.y + d.y, f2 = c.z + d.z, f3 = c.w + d.w;
            u00.x = packh2(e0 + f0, e1 + f1);
            u00.y = packh2(e2 + f2, e3 + f3);
            u01.x = packh2(e0 - f0, e1 - f1);
            u01.y = packh2(e2 - f2, e3 - f3);
            *(uint2*)(U1w + (size_t)q * 256 + j0)       = u1f;
            *(uint2*)(U1w + (size_t)q * 256 + 252 - j0) = u1r;
            *(uint2*)(U00w + (size_t)q * 128 + j0)      = u00;
            *(uint2*)(U01w + (size_t)q * 128 + j0)      = u01;
        }
    } else {
        const int eit = ODD ? 32 : 16;
#pragma unroll 1
        for (int it = 0; it < eit; ++it) {
            int idx = it * 256 + tid;
            int rl = idx >> 5, i4 = (idx & 31) * 4;
            int prow = ODD ? (2 * rl + 1) : (br == 0 ? 4 * rl : 4 * rl + 2);
            float4 v = *(float4*)(Sf + rl * SPF + i4);
            float sc = (2.0f / 512.0f) * (prow == 0 ? is2 : 1.0f);
            v.x *= sc; v.y *= sc; v.z *= sc; v.w *= sc;
            if (yb * 128 + i4 == 0) v.x *= is2;
            __stcs((float4*)(Of + (size_t)prow * DCT_N + yb * 128 + i4), v);
        }
    }
}

extern "C" void kernel_launch(void* const* d_in, const int* in_sizes, int n_in,
                              void* d_out, int out_size)
{
    const float* img = (const float*)d_in[0];
    float* out = (float*)d_out;

    static bool attr_set = false;
    if (!attr_set) {
        cudaFuncSetAttribute(dct_k<0>,
                             cudaFuncAttributeMaxDynamicSharedMemorySize, SMEM_BYTES);
        cudaFuncSetAttribute(dct_k<1>,
                             cudaFuncAttributeMaxDynamicSharedMemorySize, SMEM_BYTES);
        attr_set = true;
    }

    const int tbl_elems = 256 * 256 + 2 * 128 * 128;   // 98304
    init_tables_kernel<<<(tbl_elems + 255) / 256, 256>>>();

    dct_k<0><<<1536, 256, SMEM_BYTES>>>(img, out);   // 512 odd + 1024 even jobs
    dct_k<1><<<1536, 256, SMEM_BYTES>>>(img, out);
}

// round 11
// speedup vs baseline: 1.3915x; 1.3915x over previous
#include <cuda_runtime.h>
#include <cuda_fp16.h>
#include <cstdint>

// ---------------------------------------------------------------------------
// 2D DCT-II, two-level parity folding, fp16 mma.sync (m16n8k16, fp32 accum).
// R7 geometry (128x128 CTA tile, 64x32 warp tiles, 2 CTA/SM) with a 4-stage
// BK=32 cp.async pipeline (loads 3 chunks ahead, 1 barrier per chunk).
// Branches per pass (q = transform output index):
//   q odd   : K=256, u1  = x[n]-x[511-n],      tbl cos(pi(2n+1)(2r+1)/1024)
//   q = 4s  : K=128, u00 = lvl2(+) of lvl1(+), tbl cos(pi(2n+1)s/256)
//   q = 4s+2: K=128, u01 = lvl2(-) of lvl1(+), tbl cos(pi(2n+1)(2s+1)/512)
// Pass A CTAs cover i-quads {j0, 511-j0, 255-j0, 256+j0}; epilogue emits
// U1/U00/U01 (both fold levels in fp32) directly. Pass B is pure cp.async.
// ---------------------------------------------------------------------------

#define DCT_N 512
#define BATCH 128
#define KH    256
#define BM    128
#define BN    128
#define BKC   32
#define APH   40             // A smem pitch (halfs): 32 + 8 pad
#define BPH   136            // B smem pitch (halfs): 128 + 8 pad
#define SPF   132            // epilogue staging pitch (floats)

#define A_BYTES (BM * APH * 2)        // 10240
#define B_BYTES (BKC * BPH * 2)       // 8704
#define ST_BYTES (A_BYTES + B_BYTES)  // 18944
#define SMEM_BYTES (4 * ST_BYTES)     // 75776  (> staging 128*132*4 = 67584)

__device__ __align__(16) __half g_T1 [KH * KH];     // [n][r] cos(pi(2n+1)(2r+1)/1024)
__device__ __align__(16) __half g_TEE[128 * 128];   // [n][s] cos(pi(2n+1)s/256)
__device__ __align__(16) __half g_TEO[128 * 128];   // [n][s] cos(pi(2n+1)(2s+1)/512)
__device__ __align__(16) __half g_U1 [(size_t)BATCH * DCT_N * 256];
__device__ __align__(16) __half g_U00[(size_t)BATCH * DCT_N * 128];
__device__ __align__(16) __half g_U01[(size_t)BATCH * DCT_N * 128];

__global__ void init_tables_kernel() {
    int idx = blockIdx.x * blockDim.x + threadIdx.x;
    if (idx < KH * KH) {
        int n = idx >> 8, r = idx & 255;
        g_T1[idx] = __float2half_rn(
            cospif((2.0f * n + 1.0f) * (2.0f * r + 1.0f) * (1.0f / 1024.0f)));
    } else if (idx < KH * KH + 128 * 128) {
        int j = idx - KH * KH;
        int n = j >> 7, s = j & 127;
        g_TEE[j] = __float2half_rn(
            cospif((2.0f * n + 1.0f) * (float)s * (1.0f / 256.0f)));
    } else if (idx < KH * KH + 2 * 128 * 128) {
        int j = idx - KH * KH - 128 * 128;
        int n = j >> 7, s = j & 127;
        g_TEO[j] = __float2half_rn(
            cospif((2.0f * n + 1.0f) * (2.0f * s + 1.0f) * (1.0f / 512.0f)));
    }
}

__device__ __forceinline__ uint32_t smem_u32(const void* p) {
    uint32_t a;
    asm("{ .reg .u64 t; cvta.to.shared.u64 t, %1; cvt.u32.u64 %0, t; }" : "=r"(a) : "l"(p));
    return a;
}
__device__ __forceinline__ void cp16(uint32_t dst, const void* src) {
    asm volatile("cp.async.cg.shared.global [%0], [%1], 16;" :: "r"(dst), "l"(src));
}
#define CP_COMMIT() asm volatile("cp.async.commit_group;" ::: "memory")
#define CP_WAIT(n)  asm volatile("cp.async.wait_group %0;" :: "n"(n) : "memory")

__device__ __forceinline__ void ldsm4(uint32_t r[4], uint32_t addr) {
    asm volatile("ldmatrix.sync.aligned.m8n8.x4.shared.b16 {%0,%1,%2,%3}, [%4];"
                 : "=r"(r[0]), "=r"(r[1]), "=r"(r[2]), "=r"(r[3]) : "r"(addr));
}
__device__ __forceinline__ void ldsm4t(uint32_t r[4], uint32_t addr) {
    asm volatile("ldmatrix.sync.aligned.m8n8.x4.trans.shared.b16 {%0,%1,%2,%3}, [%4];"
                 : "=r"(r[0]), "=r"(r[1]), "=r"(r[2]), "=r"(r[3]) : "r"(addr));
}
__device__ __forceinline__ void mma_f16(float c[4], const uint32_t a[4],
                                        uint32_t b0, uint32_t b1) {
    asm volatile(
        "mma.sync.aligned.m16n8k16.row.col.f32.f16.f16.f32 "
        "{%0,%1,%2,%3},{%4,%5,%6,%7},{%8,%9},{%0,%1,%2,%3};"
        : "+f"(c[0]), "+f"(c[1]), "+f"(c[2]), "+f"(c[3])
        : "r"(a[0]), "r"(a[1]), "r"(a[2]), "r"(a[3]), "r"(b0), "r"(b1));
}
__device__ __forceinline__ uint32_t packh2(float lo, float hi) {
    __half2 h = __floats2half2_rn(lo, hi);
    return *(uint32_t*)&h;
}

// MODE 0: A-source = img (fp32, folded inline), out = U1/U00/U01 (fp16)
// MODE 1: A-source = U1/U00/U01 (pure cp.async), out = d_out (fp32, scaled)
template <int MODE>
__global__ __launch_bounds__(256, 2)
void dct_fold_fp16(const float* __restrict__ img, float* __restrict__ out)
{
    extern __shared__ __align__(16) char smem[];
    const uint32_t sb = smem_u32(smem);
    float* Sf = (float*)smem;

    const int tid = threadIdx.x, lane = tid & 31, warp = tid >> 5;
    const int jx  = blockIdx.x;          // 0,1: odd-q blocks; 2: q=4s; 3: q=4s+2
    const int bat = blockIdx.z;
    const int yb  = blockIdx.y;
    const bool ODD = (jx < 2);
    const int  NC  = ODD ? 8 : 4;        // K / 32
    const int  rC  = ODD ? jx * BN : 0;
    const int  TW  = ODD ? KH : 128;     // table row width
    const __half* tbl = ODD ? g_T1 : (jx == 2 ? g_TEE : g_TEO);
    const float sg2 = (jx == 3) ? -1.0f : 1.0f;
    const int wm = (warp & 1) * 64, wn = (warp >> 1) * 32;
    const int grp = lane >> 2, tig = lane & 3;

    const float* Ef = img + (size_t)bat * DCT_N * DCT_N;
    const __half* Ub =
        ODD ? g_U1 + (size_t)bat * DCT_N * 256
            : (jx == 2 ? g_U00 : g_U01) + (size_t)bat * DCT_N * 128;
    const int UW = ODD ? 256 : 128;
    float* Of = out + (size_t)bat * DCT_N * DCT_N;

    const int aLaneOff =
        ((wm + (lane & 7) + ((lane >> 3) & 1) * 8) * APH + (lane >> 4) * 8) * 2;
    const int bLaneOff =
        (((((lane >> 4) & 1) * 8) + (lane & 7)) * BPH + ((lane >> 3) & 1) * 8) * 2;

    float acc[4][4][4];
#pragma unroll
    for (int mi = 0; mi < 4; ++mi)
#pragma unroll
        for (int ni = 0; ni < 4; ++ni)
#pragma unroll
            for (int r = 0; r < 4; ++r) acc[mi][ni][r] = 0.0f;

    // A-loader coords: 128 rows x 4 granules(8h) -> 2 per thread
    int rowA[2], kh[2];
    const float* rowPtr[2];
#pragma unroll
    for (int i = 0; i < 2; ++i) {
        int g = tid + i * 256;
        rowA[i] = g >> 2;
        kh[i] = (g & 3) * 8;
        if (MODE == 0) {
            int l = rowA[i];
            int j0 = 32 * yb + (l & 31);
            int quad = l >> 5;
            int gi = (quad == 0) ? j0
                   : (quad == 1) ? 511 - j0
                   : (quad == 2) ? 255 - j0
                                 : 256 + j0;
            rowPtr[i] = Ef + (size_t)gi * DCT_N;
        }
    }
    // B-loader coords: 32 rows x 16 granules -> 2 per thread
    int rowB[2], nB[2];
#pragma unroll
    for (int i = 0; i < 2; ++i) {
        int g = tid + i * 256;
        rowB[i] = g >> 4;
        nB[i] = (g & 15) * 8;
    }

    uint4 oReg[2];
    auto ldA = [&](int t) {   // MODE 0 only: fold img -> fp16 regs
#pragma unroll
        for (int i = 0; i < 2; ++i) {
            int kp = t * BKC + kh[i];
            const float* base = rowPtr[i];
            float4 F0 = *(const float4*)(base + kp);
            float4 F1 = *(const float4*)(base + kp + 4);
            float4 R1 = *(const float4*)(base + 508 - kp);
            float4 R0 = *(const float4*)(base + 504 - kp);
            if (ODD) {
                oReg[i].x = packh2(F0.x - R1.w, F0.y - R1.z);
                oReg[i].y = packh2(F0.z - R1.y, F0.w - R1.x);
                oReg[i].z = packh2(F1.x - R0.w, F1.y - R0.z);
                oReg[i].w = packh2(F1.z - R0.y, F1.w - R0.x);
            } else {
                float4 C1 = *(const float4*)(base + 252 - kp);
                float4 C0 = *(const float4*)(base + 248 - kp);
                float4 D0 = *(const float4*)(base + 256 + kp);
                float4 D1 = *(const float4*)(base + 260 + kp);
                oReg[i].x = packh2(fmaf(sg2, C1.w + D0.x, F0.x + R1.w),
                                   fmaf(sg2, C1.z + D0.y, F0.y + R1.z));
                oReg[i].y = packh2(fmaf(sg2, C1.y + D0.z, F0.z + R1.y),
                                   fmaf(sg2, C1.x + D0.w, F0.w + R1.x));
                oReg[i].z = packh2(fmaf(sg2, C0.w + D1.x, F1.x + R0.w),
                                   fmaf(sg2, C0.z + D1.y, F1.y + R0.z));
                oReg[i].w = packh2(fmaf(sg2, C0.y + D1.z, F1.z + R0.y),
                                   fmaf(sg2, C0.x + D1.w, F1.w + R0.x));
            }
        }
    };
    auto stsA = [&](uint32_t off) {
#pragma unroll
        for (int i = 0; i < 2; ++i)
            *(uint4*)(smem + off + (rowA[i] * APH + kh[i]) * 2) = oReg[i];
    };
    auto cpA = [&](int t, uint32_t off) {   // MODE 1: pure async
#pragma unroll
        for (int i = 0; i < 2; ++i) {
            uint32_t dst = sb + off + (rowA[i] * APH + kh[i]) * 2;
            const __half* src = Ub + (size_t)(yb * BM + rowA[i]) * UW + t * BKC + kh[i];
            cp16(dst, src);
        }
    };
    auto cpB = [&](int t, uint32_t off) {
#pragma unroll
        for (int i = 0; i < 2; ++i) {
            uint32_t dst = sb + off + (rowB[i] * BPH + nB[i]) * 2;
            const __half* src = tbl + (size_t)(t * BKC + rowB[i]) * TW + rC + nB[i];
            cp16(dst, src);
        }
    };
    auto compute = [&](uint32_t aOff, uint32_t bOff) {
#pragma unroll
        for (int ks = 0; ks < 2; ++ks) {
            uint32_t a[4][4];
#pragma unroll
            for (int mi = 0; mi < 4; ++mi)
                ldsm4(a[mi], sb + aOff + aLaneOff + mi * (16 * APH * 2) + ks * 32);
            uint32_t bq[2][4];
#pragma unroll
            for (int pr = 0; pr < 2; ++pr)
                ldsm4t(bq[pr], sb + bOff + bLaneOff + ks * (16 * BPH * 2)
                               + (wn + pr * 16) * 2);
#pragma unroll
            for (int mi = 0; mi < 4; ++mi)
#pragma unroll
                for (int ni = 0; ni < 4; ++ni)
                    mma_f16(acc[mi][ni], a[mi],
                            bq[ni >> 1][ni & 1], bq[ni >> 1][2 + (ni & 1)]);
        }
    };

    uint32_t aOff[4], bOff[4];
#pragma unroll
    for (int s = 0; s < 4; ++s) {
        aOff[s] = s * ST_BYTES;
        bOff[s] = aOff[s] + A_BYTES;
    }

    // ---- prologue: fill 3 stages ----
    if (MODE == 0) {
        ldA(0); stsA(aOff[0]); cpB(0, bOff[0]); CP_COMMIT();
        ldA(1); stsA(aOff[1]); cpB(1, bOff[1]); CP_COMMIT();
        ldA(2); stsA(aOff[2]); cpB(2, bOff[2]); CP_COMMIT();
        ldA(3);                       // regs for chunk 3 (NC >= 4 always)
    } else {
        cpA(0, aOff[0]); cpB(0, bOff[0]); CP_COMMIT();
        cpA(1, aOff[1]); cpB(1, bOff[1]); CP_COMMIT();
        cpA(2, aOff[2]); cpB(2, bOff[2]); CP_COMMIT();
    }

    // ---- mainloop: one barrier per 32-k chunk ----
#pragma unroll 1
    for (int t = 0; t < NC; ++t) {
        if (t + 3 <= NC)      { }      // (count below)
        if (t <= NC - 3)      { CP_WAIT(2); }
        else if (t == NC - 2) { CP_WAIT(1); }
        else                  { CP_WAIT(0); }
        __syncthreads();               // chunk t ready; all warps past compute(t-1)
        if (t + 3 < NC) {
            if (MODE == 0) stsA(aOff[(t + 3) & 3]);
            else           cpA(t + 3, aOff[(t + 3) & 3]);
            cpB(t + 3, bOff[(t + 3) & 3]);
            CP_COMMIT();
            if (MODE == 0 && t + 4 < NC) ldA(t + 4);
        }
        compute(aOff[t & 3], bOff[t & 3]);
    }
    __syncthreads();

    // ---- epilogue: stage full 128x128 fp32 tile (Sf[rl][ii]) ----
#pragma unroll
    for (int mi = 0; mi < 4; ++mi)
#pragma unroll
        for (int ni = 0; ni < 4; ++ni)
#pragma unroll
            for (int h = 0; h < 2; ++h)
#pragma unroll
                for (int c = 0; c < 2; ++c) {
                    int rl = wn + ni * 8 + 2 * tig + c;
                    int ii = wm + mi * 16 + grp + 8 * h;
                    Sf[rl * SPF + ii] = acc[mi][ni][2 * h + c];
                }
    __syncthreads();

    const float is2 = 0.70710678118654752440f;
    if (MODE == 0) {
        __half* U1w  = g_U1  + (size_t)bat * DCT_N * 256;
        __half* U00w = g_U00 + (size_t)bat * DCT_N * 128;
        __half* U01w = g_U01 + (size_t)bat * DCT_N * 128;
#pragma unroll
        for (int it = 0; it < 4; ++it) {
            int idx = it * 256 + tid;
            int rl = idx >> 3;
            int jj4 = (idx & 7) * 4;
            int q = ODD ? (2 * (rC + rl) + 1) : (jx == 2 ? 4 * rl : 4 * rl + 2);
            int j0 = 32 * yb + jj4;
            const float* Sr = Sf + rl * SPF;
            float4 a = *(const float4*)(Sr + jj4);        // T[j0..]
            float4 b = *(const float4*)(Sr + 32 + jj4);   // T[511-j0..]
            float4 c = *(const float4*)(Sr + 64 + jj4);   // T[255-j0..]
            float4 d = *(const float4*)(Sr + 96 + jj4);   // T[256+j0..]
            uint2 u1f, u1r, u00, u01;
            u1f.x = packh2(a.x - b.x, a.y - b.y);
            u1f.y = packh2(a.z - b.z, a.w - b.w);
            u1r.x = packh2(c.w - d.w, c.z - d.z);
            u1r.y = packh2(c.y - d.y, c.x - d.x);
            float e0 = a.x + b.x, e1 = a.y + b.y, e2 = a.z + b.z, e3 = a.w + b.w;
            float f0 = c.x + d.x, f1 = c.y + d.y, f2 = c.z + d.z, f3 = c.w + d.w;
            u00.x = packh2(e0 + f0, e1 + f1);
            u00.y = packh2(e2 + f2, e3 + f3);
            u01.x = packh2(e0 - f0, e1 - f1);
            u01.y = packh2(e2 - f2, e3 - f3);
            *(uint2*)(U1w + (size_t)q * 256 + j0)        = u1f;
            *(uint2*)(U1w + (size_t)q * 256 + 252 - j0)  = u1r;
            *(uint2*)(U00w + (size_t)q * 128 + j0)       = u00;
            *(uint2*)(U01w + (size_t)q * 128 + j0)       = u01;
        }
    } else {
#pragma unroll
        for (int it = 0; it < 16; ++it) {
            int idx = it * 256 + tid;
            int rl = idx >> 5, i4 = (idx & 31) * 4;
            int prow = ODD ? (2 * (rC + rl) + 1) : (jx == 2 ? 4 * rl : 4 * rl + 2);
            float4 v = *(float4*)(Sf + rl * SPF + i4);
            float sc = (2.0f / 512.0f) * (prow == 0 ? is2 : 1.0f);
            v.x *= sc; v.y *= sc; v.z *= sc; v.w *= sc;
            if (yb * BM + i4 == 0) v.x *= is2;
            __stcs((float4*)(Of + (size_t)prow * DCT_N + yb * BM + i4), v);
        }
    }
}

extern "C" void kernel_launch(void* const* d_in, const int* in_sizes, int n_in,
                              void* d_out, int out_size)
{
    const float* img = (const float*)d_in[0];
    float* out = (float*)d_out;

    static bool attr_set = false;
    if (!attr_set) {
        cudaFuncSetAttribute(dct_fold_fp16<0>,
                             cudaFuncAttributeMaxDynamicSharedMemorySize, SMEM_BYTES);
        cudaFuncSetAttribute(dct_fold_fp16<1>,
                             cudaFuncAttributeMaxDynamicSharedMemorySize, SMEM_BYTES);
        attr_set = true;
    }

    const int tbl_elems = KH * KH + 2 * 128 * 128;   // 98304
    init_tables_kernel<<<(tbl_elems + 255) / 256, 256>>>();

    dim3 grid(4, 4, BATCH);   // jx: {odd0, odd1, ee, eo}
    dct_fold_fp16<0><<<grid, 256, SMEM_BYTES>>>(img, out);
    dct_fold_fp16<1><<<grid, 256, SMEM_BYTES>>>(img, out);
}